// round 14
// baseline (speedup 1.0000x reference)
#include <cuda_runtime.h>
#include <cuda_fp16.h>
#include <cstdint>

#define NHEAD 12
#define NB    64
#define NTOK  577
#define NC    768
#define ND    64
#define NKEEP 289          // tokens kept incl. CLS
#define NMASK 576
#define MROWS (NB*NTOK)    // 36928
#define QCOLS (3*NC)       // 2304
#define NPAD  296          // padded kept tokens for QK^T (37 x 8)
#define NT8   37           // n-tiles of 8
#define NPAD2 304          // padded kept tokens for PV (19 x 16)

// ---------------- scratch (static device globals; no allocations) -------------
__device__ __align__(16) __half g_qh [(size_t)NB*NHEAD*NTOK*ND];   // Q half
__device__ __align__(16) __half g_kph[(size_t)NB*NHEAD*NKEEP*ND];  // gathered K half
__device__ __align__(16) __half g_vph[(size_t)NB*NHEAD*NKEEP*ND];  // gathered V half
__device__ __align__(16) __half g_aoh[(size_t)NB*NTOK*NC];         // attn out half
__device__ int g_dest[NB*NHEAD*NTOK];                              // token -> kept slot

// ---------------- helpers ------------------------------------------------------
__device__ __forceinline__ void mma_f16(float* c, const uint32_t* a, const uint32_t* b) {
    asm volatile(
        "mma.sync.aligned.m16n8k16.row.col.f32.f16.f16.f32 "
        "{%0,%1,%2,%3}, {%4,%5,%6,%7}, {%8,%9}, {%0,%1,%2,%3};\n"
        : "+f"(c[0]), "+f"(c[1]), "+f"(c[2]), "+f"(c[3])
        : "r"(a[0]), "r"(a[1]), "r"(a[2]), "r"(a[3]), "r"(b[0]), "r"(b[1]));
}
__device__ __forceinline__ void ldsm_x4(uint32_t* r, uint32_t addr) {
    asm volatile("ldmatrix.sync.aligned.m8n8.x4.shared.b16 {%0,%1,%2,%3}, [%4];"
                 : "=r"(r[0]), "=r"(r[1]), "=r"(r[2]), "=r"(r[3]) : "r"(addr));
}
__device__ __forceinline__ void ldsm_x2(uint32_t& r0, uint32_t& r1, uint32_t addr) {
    asm volatile("ldmatrix.sync.aligned.m8n8.x2.shared.b16 {%0,%1}, [%2];"
                 : "=r"(r0), "=r"(r1) : "r"(addr));
}
__device__ __forceinline__ void ldsm_x2_trans(uint32_t& r0, uint32_t& r1, uint32_t addr) {
    asm volatile("ldmatrix.sync.aligned.m8n8.x2.trans.shared.b16 {%0,%1}, [%2];"
                 : "=r"(r0), "=r"(r1) : "r"(addr));
}
__device__ __forceinline__ uint32_t smem_u32(const void* p) {
    return (uint32_t)__cvta_generic_to_shared(p);
}

// ---------------- token selection: exact top-288 of 576 per (b,h) -------------
__global__ __launch_bounds__(256) void select_kernel(const float* __restrict__ mask)
{
    int row = blockIdx.x;                       // b*NHEAD + h
    __shared__ float v[NMASK];
    __shared__ unsigned char keep[NMASK];
    const float* mrow = mask + (size_t)row * NMASK;
    for (int i = threadIdx.x; i < NMASK; i += 256) v[i] = mrow[i];
    __syncthreads();
    for (int i = threadIdx.x; i < NMASK; i += 256) {
        float vi = v[i];
        int cnt = 0;
        for (int j = 0; j < NMASK; ++j) {
            float vj = v[j];
            cnt += (vj > vi) || (vj == vi && j < i);   // top_k tie-break: lower index wins
        }
        keep[i] = (cnt < (NKEEP - 1)) ? 1 : 0;
    }
    __syncthreads();
    if (threadIdx.x == 0) {
        int* dm = g_dest + (size_t)row * NTOK;
        dm[0] = 0;
        int pos = 0;
        for (int i = 0; i < NMASK; ++i)
            dm[1 + i] = keep[i] ? (++pos) : -1;
    }
}

// ---------------- 128x128x16 fp16 mma.sync GEMM (unchanged from R13) -----------
#define AS_H 40
#define BS_H2 136
template<int LDW, bool SCATTER, bool USE_AO>
__global__ __launch_bounds__(256, 2) void gemm_mma(const float* __restrict__ Ain,
                                                   const float* __restrict__ W,
                                                   const float* __restrict__ bias,
                                                   float* __restrict__ out)
{
    __shared__ __half  As[2][128][AS_H];
    __shared__ __half2 Bs[2][8][BS_H2];
    const int K = NC;

    int tid  = threadIdx.x;
    int brow = blockIdx.y * 128;
    int bcol = blockIdx.x * 128;

    int ar0f = tid >> 2;
    int acf  = (tid & 3) << 2;
    int ar0h = tid >> 1;
    int ach  = (tid & 1) << 3;
    int bkk = tid >> 5;
    int bn  = (tid & 31) << 2;

    int wid  = tid >> 5;
    int lane = tid & 31;
    int gid  = lane >> 2;
    int tid4 = lane & 3;
    int m0 = (wid >> 2) * 64;
    int n0 = (wid & 3) * 32;

    int la_row = lane & 15;
    int la_col = (lane >> 4) << 3;

    const float* Wp0 = W + (size_t)(2 * bkk) * LDW + bcol + bn;
    const float* Wp1 = Wp0 + LDW;
    const float4 z4 = make_float4(0.f, 0.f, 0.f, 0.f);
    const uint4  zu4 = make_uint4(0u, 0u, 0u, 0u);

    bool aokf0 = (brow + ar0f)      < MROWS;
    bool aokf1 = (brow + ar0f + 64) < MROWS;
    bool aokh  = (brow + ar0h)      < MROWS;
    const float*  Apf0 = Ain ? (Ain + (size_t)(brow + ar0f) * K + acf) : nullptr;
    const float*  Apf1 = Apf0 ? (Apf0 + (size_t)64 * K) : nullptr;
    const __half* Aph  = g_aoh + (size_t)(brow + ar0h) * K + ach;

    float4 pa0, pa1; uint4 pah;
    float4 pb0 = *(const float4*)Wp0;
    float4 pb1 = *(const float4*)Wp1;
    if (USE_AO) {
        pah = aokh ? *(const uint4*)Aph : zu4;
    } else {
        pa0 = aokf0 ? *(const float4*)Apf0 : z4;
        pa1 = aokf1 ? *(const float4*)Apf1 : z4;
    }

    {
        if (USE_AO) {
            *(uint4*)&As[0][ar0h][ach] = pah;
        } else {
            __half2 q0 = __floats2half2_rn(pa0.x, pa0.y);
            __half2 q1 = __floats2half2_rn(pa0.z, pa0.w);
            *(uint2*)&As[0][ar0f][acf] = make_uint2(*(uint32_t*)&q0, *(uint32_t*)&q1);
            __half2 q2 = __floats2half2_rn(pa1.x, pa1.y);
            __half2 q3 = __floats2half2_rn(pa1.z, pa1.w);
            *(uint2*)&As[0][ar0f + 64][acf] = make_uint2(*(uint32_t*)&q2, *(uint32_t*)&q3);
        }
        __half2 r0 = __floats2half2_rn(pb0.x, pb1.x);
        __half2 r1 = __floats2half2_rn(pb0.y, pb1.y);
        __half2 r2 = __floats2half2_rn(pb0.z, pb1.z);
        __half2 r3 = __floats2half2_rn(pb0.w, pb1.w);
        *(uint4*)&Bs[0][bkk][bn] = make_uint4(*(uint32_t*)&r0, *(uint32_t*)&r1,
                                              *(uint32_t*)&r2, *(uint32_t*)&r3);
    }
    __syncthreads();

    float c[4][4][4];
    #pragma unroll
    for (int mt = 0; mt < 4; ++mt)
        #pragma unroll
        for (int nt = 0; nt < 4; ++nt)
            #pragma unroll
            for (int r = 0; r < 4; ++r) c[mt][nt][r] = 0.f;

    int buf = 0;
    for (int kt = 16; kt <= K; kt += 16) {
        bool more = kt < K;
        if (more) {
            if (USE_AO) {
                pah = aokh ? *(const uint4*)(Aph + kt) : zu4;
            } else {
                pa0 = aokf0 ? *(const float4*)(Apf0 + kt) : z4;
                pa1 = aokf1 ? *(const float4*)(Apf1 + kt) : z4;
            }
            pb0 = *(const float4*)(Wp0 + (size_t)kt * LDW);
            pb1 = *(const float4*)(Wp1 + (size_t)kt * LDW);
        }
        {
            uint32_t asb = smem_u32(&As[buf][0][0]);
            uint32_t bf[4][2], af[4][4];
            #pragma unroll
            for (int nt = 0; nt < 4; ++nt) {
                bf[nt][0] = *(uint32_t*)&Bs[buf][tid4][n0 + nt*8 + gid];
                bf[nt][1] = *(uint32_t*)&Bs[buf][tid4 + 4][n0 + nt*8 + gid];
            }
            #pragma unroll
            for (int mt = 0; mt < 4; ++mt) {
                uint32_t addr = asb + (uint32_t)(((m0 + mt*16 + la_row) * AS_H + la_col) * 2);
                ldsm_x4(af[mt], addr);
            }
            #pragma unroll
            for (int mt = 0; mt < 4; ++mt)
                #pragma unroll
                for (int nt = 0; nt < 4; ++nt)
                    mma_f16(c[mt][nt], af[mt], bf[nt]);
        }
        if (more) {
            int nb = buf ^ 1;
            if (USE_AO) {
                *(uint4*)&As[nb][ar0h][ach] = pah;
            } else {
                __half2 q0 = __floats2half2_rn(pa0.x, pa0.y);
                __half2 q1 = __floats2half2_rn(pa0.z, pa0.w);
                *(uint2*)&As[nb][ar0f][acf] = make_uint2(*(uint32_t*)&q0, *(uint32_t*)&q1);
                __half2 q2 = __floats2half2_rn(pa1.x, pa1.y);
                __half2 q3 = __floats2half2_rn(pa1.z, pa1.w);
                *(uint2*)&As[nb][ar0f + 64][acf] = make_uint2(*(uint32_t*)&q2, *(uint32_t*)&q3);
            }
            __half2 r0 = __floats2half2_rn(pb0.x, pb1.x);
            __half2 r1 = __floats2half2_rn(pb0.y, pb1.y);
            __half2 r2 = __floats2half2_rn(pb0.z, pb1.z);
            __half2 r3 = __floats2half2_rn(pb0.w, pb1.w);
            *(uint4*)&Bs[nb][bkk][bn] = make_uint4(*(uint32_t*)&r0, *(uint32_t*)&r1,
                                                   *(uint32_t*)&r2, *(uint32_t*)&r3);
            __syncthreads();
            buf = nb;
        }
    }

    int colbase = bcol + n0;
    int s  = colbase / NC;
    int hd = colbase - s * NC;
    int h  = hd >> 6;

    #pragma unroll
    for (int mt = 0; mt < 4; ++mt) {
        #pragma unroll
        for (int half = 0; half < 2; ++half) {
            int m = brow + m0 + mt * 16 + gid + half * 8;
            if (m >= MROWS) continue;
            if (SCATTER) {
                int b  = m / NTOK;
                int n  = m - b * NTOK;
                int bh = b * NHEAD + h;
                __half* dst = nullptr;
                if (s == 0) {
                    dst = &g_qh[((size_t)bh * NTOK + n) * ND];
                } else {
                    int dest = g_dest[bh * NTOK + n];
                    if (dest >= 0)
                        dst = &((s == 1) ? g_kph : g_vph)[((size_t)bh * NKEEP + dest) * ND];
                }
                if (!dst) continue;
                int d_off = hd & 63;
                #pragma unroll
                for (int nt = 0; nt < 4; ++nt) {
                    int cl = nt * 8 + tid4 * 2;
                    float2 bv = *(const float2*)(bias + colbase + cl);
                    *(__half2*)(dst + d_off + cl) =
                        __floats2half2_rn(c[mt][nt][half*2+0] + bv.x,
                                          c[mt][nt][half*2+1] + bv.y);
                }
            } else {
                float* dst = out + (size_t)m * LDW + colbase;
                #pragma unroll
                for (int nt = 0; nt < 4; ++nt) {
                    int cl = nt * 8 + tid4 * 2;
                    float2 bv = *(const float2*)(bias + colbase + cl);
                    float2 o;
                    o.x = c[mt][nt][half*2+0] + bv.x;
                    o.y = c[mt][nt][half*2+1] + bv.y;
                    *(float2*)(dst + cl) = o;
                }
            }
        }
    }
}

// ---------------- attention: half-S softmax, 2 CTAs/SM -------------------------
// Qh/Kh/Vh: half rows stride 72. Ps: half [32][312] holds S then normalized P.
#define QK_H 72
#define PS_H 312
#define ATTN_SMEM (32*QK_H*2 + NPAD*QK_H*2 + NPAD2*QK_H*2 + 32*PS_H*2)

__global__ __launch_bounds__(256, 2) void attn_mma()
{
    extern __shared__ __align__(16) char sm[];
    __half* Qh = (__half*)sm;                          // 32 x 72
    __half* Kh = Qh + 32 * QK_H;                       // 296 x 72
    __half* Vh = Kh + NPAD * QK_H;                     // 304 x 72
    __half* Ps = Vh + NPAD2 * QK_H;                    // 32 x 312 (S then P)

    int tid  = threadIdx.x;
    int bh   = blockIdx.x;
    int wid  = tid >> 5;
    int lane = tid & 31;
    int gid  = lane >> 2;
    int t4   = lane & 3;

    int la_row = lane & 15;
    int la_col = (lane >> 4) << 3;
    int lk_row = lane & 7;
    int lk_col = ((lane >> 3) & 1) << 3;

    // ---- stage K and V once ----
    const __half* kp = g_kph + (size_t)bh * NKEEP * ND;
    const __half* vp = g_vph + (size_t)bh * NKEEP * ND;
    const uint4 zu4 = make_uint4(0u, 0u, 0u, 0u);
    for (int idx = tid; idx < NPAD2 * 8; idx += 256) {
        int m = idx >> 3, ch = (idx & 7) << 3;
        uint4 vv = (m < NKEEP) ? *(const uint4*)(vp + (size_t)m * ND + ch) : zu4;
        *(uint4*)&Vh[m * QK_H + ch] = vv;
        if (m < NPAD) {
            uint4 kv = (m < NKEEP) ? *(const uint4*)(kp + (size_t)m * ND + ch) : zu4;
            *(uint4*)&Kh[m * QK_H + ch] = kv;
        }
    }
    // zero Ps pad cols [NPAD, NPAD2) once (cols NKEEP..NPAD are written 0 by Phase A)
    for (int idx = tid; idx < 32 * (NPAD2 - NPAD); idx += 256) {
        int r = idx / (NPAD2 - NPAD), cl = NPAD + idx % (NPAD2 - NPAD);
        Ps[r * PS_H + cl] = __float2half(0.f);
    }
    const __half* qp = g_qh + (size_t)bh * NTOK * ND;
    int b = bh / NHEAD, h = bh - b * NHEAD;
    uint32_t qh_base = smem_u32(Qh);
    uint32_t kh_base = smem_u32(Kh);
    uint32_t vh_base = smem_u32(Vh);
    uint32_t ps_base = smem_u32(Ps);

    for (int q0 = 0; q0 < NTOK; q0 += 32) {
        {
            int m = tid >> 3, ch = (tid & 7) << 3;
            int qg = q0 + m;
            uint4 qv = (qg < NTOK) ? *(const uint4*)(qp + (size_t)qg * ND + ch) : zu4;
            *(uint4*)&Qh[m * QK_H + ch] = qv;
        }
        __syncthreads();

        // Phase A: S = (Q K^T) * scale -> half into Ps
        {
            int wm = wid & 1, wn = wid >> 1;
            int m0 = wm * 16;
            float c[10][4];
            #pragma unroll
            for (int i = 0; i < 10; ++i)
                c[i][0] = c[i][1] = c[i][2] = c[i][3] = 0.f;
            #pragma unroll
            for (int ks = 0; ks < 4; ++ks) {
                int k0 = ks * 16;
                uint32_t a[4];
                ldsm_x4(a, qh_base + (uint32_t)(((m0 + la_row) * QK_H + k0 + la_col) * 2));
                #pragma unroll
                for (int i = 0; i < 10; ++i) {
                    int nt = wn + 4 * i;
                    if (nt >= NT8) break;
                    int nb = nt * 8;
                    uint32_t bb[2];
                    ldsm_x2(bb[0], bb[1],
                            kh_base + (uint32_t)(((nb + lk_row) * QK_H + k0 + lk_col) * 2));
                    mma_f16(c[i], a, bb);
                }
            }
            #pragma unroll
            for (int i = 0; i < 10; ++i) {
                int nt = wn + 4 * i;
                if (nt >= NT8) break;
                int nb = nt * 8;
                *(__half2*)&Ps[(m0 + gid) * PS_H + nb + 2 * t4]
                    = __floats2half2_rn(c[i][0] * 0.125f, c[i][1] * 0.125f);
                *(__half2*)&Ps[(m0 + gid + 8) * PS_H + nb + 2 * t4]
                    = __floats2half2_rn(c[i][2] * 0.125f, c[i][3] * 0.125f);
            }
        }
        __syncthreads();

        // Phase B: row softmax (no max pass — values are small), in-place half
        {
            int w = tid >> 5, ln = tid & 31;
            #pragma unroll
            for (int r = 0; r < 4; ++r) {
                __half* Pr = Ps + (w * 4 + r) * PS_H;
                float sum = 0.f;
                for (int m = ln; m < NKEEP; m += 32)
                    sum += __expf(__half2float(Pr[m]));
                #pragma unroll
                for (int o = 16; o; o >>= 1) sum += __shfl_xor_sync(0xffffffffu, sum, o);
                float inv = 1.f / sum;
                for (int m = ln; m < NKEEP; m += 32)
                    Pr[m] = __float2half(__expf(__half2float(Pr[m])) * inv);
            }
        }
        __syncthreads();

        // Phase C: O = P @ V
        {
            int wm = wid & 1, wn = wid >> 1;
            int m0 = wm * 16, n0 = wn * 16;
            float c[2][4];
            #pragma unroll
            for (int nt = 0; nt < 2; ++nt)
                #pragma unroll
                for (int r = 0; r < 4; ++r) c[nt][r] = 0.f;

            int lrow = (lane & 7) + ((lane >> 3) & 1) * 8;

            for (int ks = 0; ks < NPAD2 / 16; ++ks) {
                int k0 = ks * 16;
                uint32_t a[4];
                ldsm_x4(a, ps_base + (uint32_t)(((m0 + la_row) * PS_H + k0 + la_col) * 2));
                #pragma unroll
                for (int nt = 0; nt < 2; ++nt) {
                    uint32_t bb[2];
                    uint32_t addr = vh_base + (uint32_t)(((k0 + lrow) * QK_H + n0 + nt * 8) * 2);
                    ldsm_x2_trans(bb[0], bb[1], addr);
                    mma_f16(c[nt], a, bb);
                }
            }

            #pragma unroll
            for (int half = 0; half < 2; ++half) {
                int qg = q0 + m0 + gid + half * 8;
                if (qg >= NTOK) continue;
                __half* dst = &g_aoh[((size_t)(b * NTOK + qg)) * NC + h * ND + n0];
                #pragma unroll
                for (int nt = 0; nt < 2; ++nt) {
                    *(__half2*)(dst + nt * 8 + 2 * t4) =
                        __floats2half2_rn(c[nt][half*2+0], c[nt][half*2+1]);
                }
            }
        }
        __syncthreads();
    }
}

// ---------------- launch -------------------------------------------------------
extern "C" void kernel_launch(void* const* d_in, const int* in_sizes, int n_in,
                              void* d_out, int out_size)
{
    const float* x     = (const float*)d_in[0];
    const float* mask  = (const float*)d_in[1];
    const float* Wqkv  = (const float*)d_in[2];
    const float* bqkv  = (const float*)d_in[3];
    const float* Wproj = (const float*)d_in[4];
    const float* bproj = (const float*)d_in[5];
    float* out = (float*)d_out;

    select_kernel<<<NB * NHEAD, 256>>>(mask);

    dim3 g1(QCOLS / 128, (MROWS + 127) / 128);
    gemm_mma<QCOLS, true, false><<<g1, 256>>>(x, Wqkv, bqkv, nullptr);

    cudaFuncSetAttribute(attn_mma, cudaFuncAttributeMaxDynamicSharedMemorySize, ATTN_SMEM);
    attn_mma<<<NB * NHEAD, 256, ATTN_SMEM>>>();

    dim3 g2(NC / 128, (MROWS + 127) / 128);
    gemm_mma<NC, false, true><<<g2, 256>>>(nullptr, Wproj, bproj, out);
}

// round 15
// speedup vs baseline: 1.2690x; 1.2690x over previous
#include <cuda_runtime.h>
#include <cuda_fp16.h>
#include <cstdint>

#define NHEAD 12
#define NB    64
#define NTOK  577
#define NC    768
#define ND    64
#define NKEEP 289          // tokens kept incl. CLS
#define NMASK 576
#define MROWS (NB*NTOK)    // 36928
#define QCOLS (3*NC)       // 2304
#define NPAD  296          // padded kept tokens for QK^T (37 x 8)
#define NT8   37           // n-tiles of 8
#define NPAD2 304          // padded kept tokens for PV (19 x 16)
#define NKT   48           // 768/16 k-tiles

// ---------------- scratch (static device globals; no allocations) -------------
__device__ __align__(16) __half g_xh  [(size_t)MROWS*NC];          // x as half
__device__ __align__(16) __half g_wqkvh[(size_t)NC*QCOLS];         // Wqkv half
__device__ __align__(16) __half g_wprojh[(size_t)NC*NC];           // Wproj half
__device__ __align__(16) __half g_qh [(size_t)NB*NHEAD*NTOK*ND];   // Q half
__device__ __align__(16) __half g_kph[(size_t)NB*NHEAD*NKEEP*ND];  // gathered K half
__device__ __align__(16) __half g_vph[(size_t)NB*NHEAD*NKEEP*ND];  // gathered V half
__device__ __align__(16) __half g_aoh[(size_t)NB*NTOK*NC];         // attn out half
__device__ int g_dest[NB*NHEAD*NTOK];                              // token -> kept slot

// ---------------- helpers ------------------------------------------------------
__device__ __forceinline__ void mma_f16(float* c, const uint32_t* a, const uint32_t* b) {
    asm volatile(
        "mma.sync.aligned.m16n8k16.row.col.f32.f16.f16.f32 "
        "{%0,%1,%2,%3}, {%4,%5,%6,%7}, {%8,%9}, {%0,%1,%2,%3};\n"
        : "+f"(c[0]), "+f"(c[1]), "+f"(c[2]), "+f"(c[3])
        : "r"(a[0]), "r"(a[1]), "r"(a[2]), "r"(a[3]), "r"(b[0]), "r"(b[1]));
}
__device__ __forceinline__ void ldsm_x4(uint32_t* r, uint32_t addr) {
    asm volatile("ldmatrix.sync.aligned.m8n8.x4.shared.b16 {%0,%1,%2,%3}, [%4];"
                 : "=r"(r[0]), "=r"(r[1]), "=r"(r[2]), "=r"(r[3]) : "r"(addr));
}
__device__ __forceinline__ void ldsm_x2(uint32_t& r0, uint32_t& r1, uint32_t addr) {
    asm volatile("ldmatrix.sync.aligned.m8n8.x2.shared.b16 {%0,%1}, [%2];"
                 : "=r"(r0), "=r"(r1) : "r"(addr));
}
__device__ __forceinline__ void ldsm_x2_trans(uint32_t& r0, uint32_t& r1, uint32_t addr) {
    asm volatile("ldmatrix.sync.aligned.m8n8.x2.trans.shared.b16 {%0,%1}, [%2];"
                 : "=r"(r0), "=r"(r1) : "r"(addr));
}
__device__ __forceinline__ uint32_t smem_u32(const void* p) {
    return (uint32_t)__cvta_generic_to_shared(p);
}
__device__ __forceinline__ void cp16(uint32_t dst, const void* src, bool pred) {
    int sz = pred ? 16 : 0;
    asm volatile("cp.async.cg.shared.global [%0], [%1], 16, %2;\n"
                 :: "r"(dst), "l"(src), "r"(sz));
}
__device__ __forceinline__ void cp_commit() {
    asm volatile("cp.async.commit_group;\n" ::: "memory");
}
__device__ __forceinline__ void cp_wait1() {
    asm volatile("cp.async.wait_group 1;\n" ::: "memory");
}

// ---------------- fp32 -> fp16 convert ------------------------------------------
__global__ __launch_bounds__(256) void f2h_kernel(const float* __restrict__ in,
                                                  __half* __restrict__ out, int n)
{
    int i = (blockIdx.x * 256 + threadIdx.x) * 4;
    if (i < n) {
        float4 v = *(const float4*)(in + i);
        __half2 a = __floats2half2_rn(v.x, v.y);
        __half2 b = __floats2half2_rn(v.z, v.w);
        *(uint2*)(out + i) = make_uint2(*(uint32_t*)&a, *(uint32_t*)&b);
    }
}

// ---------------- token selection: exact top-288 of 576 per (b,h) -------------
__global__ __launch_bounds__(256) void select_kernel(const float* __restrict__ mask)
{
    int row = blockIdx.x;                       // b*NHEAD + h
    __shared__ float v[NMASK];
    __shared__ unsigned char keep[NMASK];
    const float* mrow = mask + (size_t)row * NMASK;
    for (int i = threadIdx.x; i < NMASK; i += 256) v[i] = mrow[i];
    __syncthreads();
    for (int i = threadIdx.x; i < NMASK; i += 256) {
        float vi = v[i];
        int cnt = 0;
        for (int j = 0; j < NMASK; ++j) {
            float vj = v[j];
            cnt += (vj > vi) || (vj == vi && j < i);   // top_k tie-break: lower index wins
        }
        keep[i] = (cnt < (NKEEP - 1)) ? 1 : 0;
    }
    __syncthreads();
    if (threadIdx.x == 0) {
        int* dm = g_dest + (size_t)row * NTOK;
        dm[0] = 0;
        int pos = 0;
        for (int i = 0; i < NMASK; ++i)
            dm[1 + i] = keep[i] ? (++pos) : -1;
    }
}

// ---------------- 128x128x16 fp16 GEMM, 3-stage cp.async pipeline ---------------
// As: [m][40] halfs, ldmatrix.x4 frags. Bs: [k][136] halfs, ldmatrix.x2.trans.
#define AS_H 40
#define BS_H 136
template<int LDW, bool SCATTER>
__global__ __launch_bounds__(256, 2) void gemm_cp(const __half* __restrict__ A,
                                                  const __half* __restrict__ W,
                                                  const float* __restrict__ bias,
                                                  float* __restrict__ out)
{
    __shared__ __half As[3][128][AS_H];
    __shared__ __half Bs[3][16][BS_H];

    int tid  = threadIdx.x;
    int brow = blockIdx.y * 128;
    int bcol = blockIdx.x * 128;

    // cp.async coords: A row tid>>1, 8-half chunk (tid&1); B row tid>>4, chunk tid&15
    int arow = tid >> 1;
    int acol = (tid & 1) << 3;
    int brw  = tid >> 4;
    int bcl  = (tid & 15) << 3;
    bool aok = (brow + arow) < MROWS;
    const __half* Ap = A + (size_t)(brow + arow) * NC + acol;
    const __half* Wp = W + (size_t)brw * LDW + bcol + bcl;

    int wid  = tid >> 5;
    int lane = tid & 31;
    int gid  = lane >> 2;
    int tid4 = lane & 3;
    int m0 = (wid >> 2) * 64;
    int n0 = (wid & 3) * 32;
    int la_row = lane & 15;
    int la_col = (lane >> 4) << 3;
    int lrowB  = (lane & 7) + ((lane >> 3) & 1) * 8;   // k-row for B trans frags

    uint32_t as_addr[3], bs_addr[3];
    #pragma unroll
    for (int s = 0; s < 3; ++s) {
        as_addr[s] = smem_u32(&As[s][arow][acol]);
        bs_addr[s] = smem_u32(&Bs[s][brw][bcl]);
    }

    // prologue: stages 0,1
    #pragma unroll
    for (int s = 0; s < 2; ++s) {
        cp16(as_addr[s], Ap + s * 16, aok);
        cp16(bs_addr[s], Wp + (size_t)(s * 16) * LDW, true);
        cp_commit();
    }

    float c[4][4][4];
    #pragma unroll
    for (int mt = 0; mt < 4; ++mt)
        #pragma unroll
        for (int nt = 0; nt < 4; ++nt)
            #pragma unroll
            for (int r = 0; r < 4; ++r) c[mt][nt][r] = 0.f;

    for (int t = 0; t < NKT; ++t) {
        cp_wait1();
        __syncthreads();
        // issue stage t+2
        if (t + 2 < NKT) {
            int s = (t + 2) % 3;
            cp16(as_addr[s], Ap + (t + 2) * 16, aok);
            cp16(bs_addr[s], Wp + (size_t)((t + 2) * 16) * LDW, true);
        }
        cp_commit();

        // compute stage t
        int s = t % 3;
        uint32_t asb = smem_u32(&As[s][0][0]);
        uint32_t bsb = smem_u32(&Bs[s][0][0]);
        uint32_t af[4][4], bf[4][2];
        #pragma unroll
        for (int mt = 0; mt < 4; ++mt)
            ldsm_x4(af[mt], asb + (uint32_t)(((m0 + mt*16 + la_row) * AS_H + la_col) * 2));
        #pragma unroll
        for (int nt = 0; nt < 4; ++nt)
            ldsm_x2_trans(bf[nt][0], bf[nt][1],
                          bsb + (uint32_t)((lrowB * BS_H + n0 + nt * 8) * 2));
        #pragma unroll
        for (int mt = 0; mt < 4; ++mt)
            #pragma unroll
            for (int nt = 0; nt < 4; ++nt)
                mma_f16(c[mt][nt], af[mt], bf[nt]);
        __syncthreads();
    }

    // ---------------- epilogue (R13 layout) ----------------
    int colbase = bcol + n0;
    int s  = colbase / NC;
    int hd = colbase - s * NC;
    int h  = hd >> 6;

    #pragma unroll
    for (int mt = 0; mt < 4; ++mt) {
        #pragma unroll
        for (int half = 0; half < 2; ++half) {
            int m = brow + m0 + mt * 16 + gid + half * 8;
            if (m >= MROWS) continue;
            if (SCATTER) {
                int b  = m / NTOK;
                int n  = m - b * NTOK;
                int bh = b * NHEAD + h;
                __half* dst = nullptr;
                if (s == 0) {
                    dst = &g_qh[((size_t)bh * NTOK + n) * ND];
                } else {
                    int dest = g_dest[bh * NTOK + n];
                    if (dest >= 0)
                        dst = &((s == 1) ? g_kph : g_vph)[((size_t)bh * NKEEP + dest) * ND];
                }
                if (!dst) continue;
                int d_off = hd & 63;
                #pragma unroll
                for (int nt = 0; nt < 4; ++nt) {
                    int cl = nt * 8 + tid4 * 2;
                    float2 bv = *(const float2*)(bias + colbase + cl);
                    *(__half2*)(dst + d_off + cl) =
                        __floats2half2_rn(c[mt][nt][half*2+0] + bv.x,
                                          c[mt][nt][half*2+1] + bv.y);
                }
            } else {
                float* dst = out + (size_t)m * LDW + colbase;
                #pragma unroll
                for (int nt = 0; nt < 4; ++nt) {
                    int cl = nt * 8 + tid4 * 2;
                    float2 bv = *(const float2*)(bias + colbase + cl);
                    float2 o;
                    o.x = c[mt][nt][half*2+0] + bv.x;
                    o.y = c[mt][nt][half*2+1] + bv.y;
                    *(float2*)(dst + cl) = o;
                }
            }
        }
    }
}

// ---------------- attention: R13 version (verified @1448) -----------------------
#define QK_H 72
#define SS_STR 300
#define PS_H 312
#define ATTN_SMEM (32*QK_H*2 + NPAD*QK_H*2 + NPAD2*QK_H*2 + 32*SS_STR*4 + 32*PS_H*2)

__global__ __launch_bounds__(256) void attn_mma()
{
    extern __shared__ __align__(16) char sm[];
    __half* Qh = (__half*)sm;                          // 32 x 72
    __half* Kh = Qh + 32 * QK_H;                       // 296 x 72
    __half* Vh = Kh + NPAD * QK_H;                     // 304 x 72
    float*  Ss = (float*)(Vh + NPAD2 * QK_H);          // 32 x 300
    __half* Ps = (__half*)(Ss + 32 * SS_STR);          // 32 x 312

    int tid  = threadIdx.x;
    int bh   = blockIdx.x;
    int wid  = tid >> 5;
    int lane = tid & 31;
    int gid  = lane >> 2;
    int t4   = lane & 3;

    int la_row = lane & 15;
    int la_col = (lane >> 4) << 3;
    int lk_row = lane & 7;
    int lk_col = ((lane >> 3) & 1) << 3;

    const __half* kp = g_kph + (size_t)bh * NKEEP * ND;
    const __half* vp = g_vph + (size_t)bh * NKEEP * ND;
    const uint4 zu4 = make_uint4(0u, 0u, 0u, 0u);
    for (int idx = tid; idx < NPAD2 * 8; idx += 256) {
        int m = idx >> 3, ch = (idx & 7) << 3;
        uint4 vv = (m < NKEEP) ? *(const uint4*)(vp + (size_t)m * ND + ch) : zu4;
        *(uint4*)&Vh[m * QK_H + ch] = vv;
        if (m < NPAD) {
            uint4 kv = (m < NKEEP) ? *(const uint4*)(kp + (size_t)m * ND + ch) : zu4;
            *(uint4*)&Kh[m * QK_H + ch] = kv;
        }
    }
    for (int idx = tid; idx < 32 * (NPAD2 - NKEEP); idx += 256) {
        int r = idx / (NPAD2 - NKEEP), cl = NKEEP + idx % (NPAD2 - NKEEP);
        Ps[r * PS_H + cl] = __float2half(0.f);
    }
    const __half* qp = g_qh + (size_t)bh * NTOK * ND;
    int b = bh / NHEAD, h = bh - b * NHEAD;
    uint32_t qh_base = smem_u32(Qh);
    uint32_t kh_base = smem_u32(Kh);
    uint32_t vh_base = smem_u32(Vh);
    uint32_t ps_base = smem_u32(Ps);

    for (int q0 = 0; q0 < NTOK; q0 += 32) {
        {
            int m = tid >> 3, ch = (tid & 7) << 3;
            int qg = q0 + m;
            uint4 qv = (qg < NTOK) ? *(const uint4*)(qp + (size_t)qg * ND + ch) : zu4;
            *(uint4*)&Qh[m * QK_H + ch] = qv;
        }
        __syncthreads();

        // Phase A: S = (Q K^T) * scale; Q via ldsm.x4, K via ldsm.x2
        {
            int wm = wid & 1, wn = wid >> 1;
            int m0 = wm * 16;
            float c[10][4];
            #pragma unroll
            for (int i = 0; i < 10; ++i)
                c[i][0] = c[i][1] = c[i][2] = c[i][3] = 0.f;
            #pragma unroll
            for (int ks = 0; ks < 4; ++ks) {
                int k0 = ks * 16;
                uint32_t a[4];
                ldsm_x4(a, qh_base + (uint32_t)(((m0 + la_row) * QK_H + k0 + la_col) * 2));
                #pragma unroll
                for (int i = 0; i < 10; ++i) {
                    int nt = wn + 4 * i;
                    if (nt >= NT8) break;
                    int nb = nt * 8;
                    uint32_t bb[2];
                    ldsm_x2(bb[0], bb[1],
                            kh_base + (uint32_t)(((nb + lk_row) * QK_H + k0 + lk_col) * 2));
                    mma_f16(c[i], a, bb);
                }
            }
            #pragma unroll
            for (int i = 0; i < 10; ++i) {
                int nt = wn + 4 * i;
                if (nt >= NT8) break;
                int nb = nt * 8;
                *(float2*)&Ss[(m0 + gid) * SS_STR + nb + 2 * t4]
                    = make_float2(c[i][0] * 0.125f, c[i][1] * 0.125f);
                *(float2*)&Ss[(m0 + gid + 8) * SS_STR + nb + 2 * t4]
                    = make_float2(c[i][2] * 0.125f, c[i][3] * 0.125f);
            }
        }
        __syncthreads();

        // Phase B: row softmax (f32), emit normalized P as half
        {
            int w = tid >> 5, ln = tid & 31;
            #pragma unroll
            for (int r = 0; r < 4; ++r) {
                int row = w * 4 + r;
                float* Sr = Ss + row * SS_STR;
                __half* Pr = Ps + row * PS_H;
                float mx = -3.0e38f;
                for (int m = ln; m < NKEEP; m += 32) mx = fmaxf(mx, Sr[m]);
                #pragma unroll
                for (int o = 16; o; o >>= 1) mx = fmaxf(mx, __shfl_xor_sync(0xffffffffu, mx, o));
                float sum = 0.f;
                for (int m = ln; m < NKEEP; m += 32) {
                    float e = __expf(Sr[m] - mx);
                    Sr[m] = e;
                    sum += e;
                }
                #pragma unroll
                for (int o = 16; o; o >>= 1) sum += __shfl_xor_sync(0xffffffffu, sum, o);
                float inv = 1.f / sum;
                for (int m = ln; m < NKEEP; m += 32)
                    Pr[m] = __float2half(Sr[m] * inv);
            }
        }
        __syncthreads();

        // Phase C: O = P @ V; P via ldsm.x4, V via ldsm.x2.trans
        {
            int wm = wid & 1, wn = wid >> 1;
            int m0 = wm * 16, n0 = wn * 16;
            float c[2][4];
            #pragma unroll
            for (int nt = 0; nt < 2; ++nt)
                #pragma unroll
                for (int r = 0; r < 4; ++r) c[nt][r] = 0.f;

            int lrow = (lane & 7) + ((lane >> 3) & 1) * 8;

            for (int ks = 0; ks < NPAD2 / 16; ++ks) {
                int k0 = ks * 16;
                uint32_t a[4];
                ldsm_x4(a, ps_base + (uint32_t)(((m0 + la_row) * PS_H + k0 + la_col) * 2));
                #pragma unroll
                for (int nt = 0; nt < 2; ++nt) {
                    uint32_t bb[2];
                    uint32_t addr = vh_base + (uint32_t)(((k0 + lrow) * QK_H + n0 + nt * 8) * 2);
                    ldsm_x2_trans(bb[0], bb[1], addr);
                    mma_f16(c[nt], a, bb);
                }
            }

            #pragma unroll
            for (int half = 0; half < 2; ++half) {
                int qg = q0 + m0 + gid + half * 8;
                if (qg >= NTOK) continue;
                __half* dst = &g_aoh[((size_t)(b * NTOK + qg)) * NC + h * ND + n0];
                #pragma unroll
                for (int nt = 0; nt < 2; ++nt) {
                    *(__half2*)(dst + nt * 8 + 2 * t4) =
                        __floats2half2_rn(c[nt][half*2+0], c[nt][half*2+1]);
                }
            }
        }
        __syncthreads();
    }
}

// ---------------- launch -------------------------------------------------------
extern "C" void kernel_launch(void* const* d_in, const int* in_sizes, int n_in,
                              void* d_out, int out_size)
{
    const float* x     = (const float*)d_in[0];
    const float* mask  = (const float*)d_in[1];
    const float* Wqkv  = (const float*)d_in[2];
    const float* bqkv  = (const float*)d_in[3];
    const float* Wproj = (const float*)d_in[4];
    const float* bproj = (const float*)d_in[5];
    float* out = (float*)d_out;

    __half *xh, *wqkvh, *wprojh, *aoh;
    cudaGetSymbolAddress((void**)&xh,     g_xh);
    cudaGetSymbolAddress((void**)&wqkvh,  g_wqkvh);
    cudaGetSymbolAddress((void**)&wprojh, g_wprojh);
    cudaGetSymbolAddress((void**)&aoh,    g_aoh);

    {
        int n1 = MROWS * NC, n2 = NC * QCOLS, n3 = NC * NC;
        f2h_kernel<<<(n1 / 4 + 255) / 256, 256>>>(x,     xh,     n1);
        f2h_kernel<<<(n2 / 4 + 255) / 256, 256>>>(Wqkv,  wqkvh,  n2);
        f2h_kernel<<<(n3 / 4 + 255) / 256, 256>>>(Wproj, wprojh, n3);
    }

    select_kernel<<<NB * NHEAD, 256>>>(mask);

    dim3 g1(QCOLS / 128, (MROWS + 127) / 128);
    gemm_cp<QCOLS, true><<<g1, 256>>>(xh, wqkvh, bqkv, nullptr);

    cudaFuncSetAttribute(attn_mma, cudaFuncAttributeMaxDynamicSharedMemorySize, ATTN_SMEM);
    attn_mma<<<NB * NHEAD, 256, ATTN_SMEM>>>();

    dim3 g2(NC / 128, (MROWS + 127) / 128);
    gemm_cp<NC, false><<<g2, 256>>>(aoh, wprojh, bproj, out);
}

// round 16
// speedup vs baseline: 1.5790x; 1.2443x over previous
#include <cuda_runtime.h>
#include <cuda_fp16.h>
#include <cstdint>

#define NHEAD 12
#define NB    64
#define NTOK  577
#define NC    768
#define ND    64
#define NKEEP 289          // tokens kept incl. CLS
#define NMASK 576
#define MROWS (NB*NTOK)    // 36928
#define QCOLS (3*NC)       // 2304
#define NPAD  296          // padded kept tokens for QK^T (37 x 8)
#define NT8   37           // n-tiles of 8
#define NPAD2 304          // padded kept tokens for PV (19 x 16)
#define NKT   48           // 768/16 k-tiles

// ---------------- scratch (static device globals; no allocations) -------------
__device__ __align__(16) __half g_xh  [(size_t)MROWS*NC];          // x as half
__device__ __align__(16) __half g_wqkvh[(size_t)NC*QCOLS];         // Wqkv half
__device__ __align__(16) __half g_wprojh[(size_t)NC*NC];           // Wproj half
__device__ __align__(16) __half g_qh [(size_t)NB*NHEAD*NTOK*ND];   // Q half
__device__ __align__(16) __half g_kph[(size_t)NB*NHEAD*NKEEP*ND];  // gathered K half
__device__ __align__(16) __half g_vph[(size_t)NB*NHEAD*NKEEP*ND];  // gathered V half
__device__ __align__(16) __half g_aoh[(size_t)NB*NTOK*NC];         // attn out half
__device__ int g_dest[NB*NHEAD*NTOK];                              // token -> kept slot

// ---------------- helpers ------------------------------------------------------
__device__ __forceinline__ void mma_f16(float* c, const uint32_t* a, const uint32_t* b) {
    asm volatile(
        "mma.sync.aligned.m16n8k16.row.col.f32.f16.f16.f32 "
        "{%0,%1,%2,%3}, {%4,%5,%6,%7}, {%8,%9}, {%0,%1,%2,%3};\n"
        : "+f"(c[0]), "+f"(c[1]), "+f"(c[2]), "+f"(c[3])
        : "r"(a[0]), "r"(a[1]), "r"(a[2]), "r"(a[3]), "r"(b[0]), "r"(b[1]));
}
__device__ __forceinline__ void ldsm_x4(uint32_t* r, uint32_t addr) {
    asm volatile("ldmatrix.sync.aligned.m8n8.x4.shared.b16 {%0,%1,%2,%3}, [%4];"
                 : "=r"(r[0]), "=r"(r[1]), "=r"(r[2]), "=r"(r[3]) : "r"(addr));
}
__device__ __forceinline__ void ldsm_x2(uint32_t& r0, uint32_t& r1, uint32_t addr) {
    asm volatile("ldmatrix.sync.aligned.m8n8.x2.shared.b16 {%0,%1}, [%2];"
                 : "=r"(r0), "=r"(r1) : "r"(addr));
}
__device__ __forceinline__ void ldsm_x2_trans(uint32_t& r0, uint32_t& r1, uint32_t addr) {
    asm volatile("ldmatrix.sync.aligned.m8n8.x2.trans.shared.b16 {%0,%1}, [%2];"
                 : "=r"(r0), "=r"(r1) : "r"(addr));
}
__device__ __forceinline__ uint32_t smem_u32(const void* p) {
    return (uint32_t)__cvta_generic_to_shared(p);
}
__device__ __forceinline__ void cp16(uint32_t dst, const void* src, bool pred) {
    int sz = pred ? 16 : 0;
    asm volatile("cp.async.cg.shared.global [%0], [%1], 16, %2;\n"
                 :: "r"(dst), "l"(src), "r"(sz));
}
__device__ __forceinline__ void cp_commit() {
    asm volatile("cp.async.commit_group;\n" ::: "memory");
}
__device__ __forceinline__ void cp_wait1() {
    asm volatile("cp.async.wait_group 1;\n" ::: "memory");
}

// ---------------- fp32 -> fp16 convert ------------------------------------------
__global__ __launch_bounds__(256) void f2h_kernel(const float* __restrict__ in,
                                                  __half* __restrict__ out, int n)
{
    int i = (blockIdx.x * 256 + threadIdx.x) * 4;
    if (i < n) {
        float4 v = *(const float4*)(in + i);
        __half2 a = __floats2half2_rn(v.x, v.y);
        __half2 b = __floats2half2_rn(v.z, v.w);
        *(uint2*)(out + i) = make_uint2(*(uint32_t*)&a, *(uint32_t*)&b);
    }
}

// ---------------- token selection: exact top-288 of 576 per (b,h) -------------
__global__ __launch_bounds__(256) void select_kernel(const float* __restrict__ mask)
{
    int row = blockIdx.x;                       // b*NHEAD + h
    __shared__ __align__(16) float v[NMASK];
    __shared__ unsigned char keep[NMASK];
    const float* mrow = mask + (size_t)row * NMASK;
    for (int i = threadIdx.x; i < NMASK; i += 256) v[i] = mrow[i];
    __syncthreads();
    for (int i = threadIdx.x; i < NMASK; i += 256) {
        float vi = v[i];
        int cnt = 0;
        #pragma unroll 4
        for (int j = 0; j < NMASK; j += 4) {
            float4 vj = *(const float4*)&v[j];
            cnt += (vj.x > vi) || (vj.x == vi && (j + 0) < i);
            cnt += (vj.y > vi) || (vj.y == vi && (j + 1) < i);
            cnt += (vj.z > vi) || (vj.z == vi && (j + 2) < i);
            cnt += (vj.w > vi) || (vj.w == vi && (j + 3) < i);
        }
        keep[i] = (cnt < (NKEEP - 1)) ? 1 : 0;
    }
    __syncthreads();
    if (threadIdx.x == 0) {
        int* dm = g_dest + (size_t)row * NTOK;
        dm[0] = 0;
        int pos = 0;
        for (int i = 0; i < NMASK; ++i)
            dm[1 + i] = keep[i] ? (++pos) : -1;
    }
}

// ---------------- 128x128x16 fp16 GEMM, 3-stage cp.async (R15, proven) ----------
#define AS_H 40
#define BS_H 136
template<int LDW, bool SCATTER>
__global__ __launch_bounds__(256, 2) void gemm_cp(const __half* __restrict__ A,
                                                  const __half* __restrict__ W,
                                                  const float* __restrict__ bias,
                                                  float* __restrict__ out)
{
    __shared__ __half As[3][128][AS_H];
    __shared__ __half Bs[3][16][BS_H];

    int tid  = threadIdx.x;
    int brow = blockIdx.y * 128;
    int bcol = blockIdx.x * 128;

    int arow = tid >> 1;
    int acol = (tid & 1) << 3;
    int brw  = tid >> 4;
    int bcl  = (tid & 15) << 3;
    bool aok = (brow + arow) < MROWS;
    const __half* Ap = A + (size_t)(brow + arow) * NC + acol;
    const __half* Wp = W + (size_t)brw * LDW + bcol + bcl;

    int wid  = tid >> 5;
    int lane = tid & 31;
    int gid  = lane >> 2;
    int tid4 = lane & 3;
    int m0 = (wid >> 2) * 64;
    int n0 = (wid & 3) * 32;
    int la_row = lane & 15;
    int la_col = (lane >> 4) << 3;
    int lrowB  = (lane & 7) + ((lane >> 3) & 1) * 8;

    uint32_t as_addr[3], bs_addr[3];
    #pragma unroll
    for (int s = 0; s < 3; ++s) {
        as_addr[s] = smem_u32(&As[s][arow][acol]);
        bs_addr[s] = smem_u32(&Bs[s][brw][bcl]);
    }

    #pragma unroll
    for (int s = 0; s < 2; ++s) {
        cp16(as_addr[s], Ap + s * 16, aok);
        cp16(bs_addr[s], Wp + (size_t)(s * 16) * LDW, true);
        cp_commit();
    }

    float c[4][4][4];
    #pragma unroll
    for (int mt = 0; mt < 4; ++mt)
        #pragma unroll
        for (int nt = 0; nt < 4; ++nt)
            #pragma unroll
            for (int r = 0; r < 4; ++r) c[mt][nt][r] = 0.f;

    for (int t = 0; t < NKT; ++t) {
        cp_wait1();
        __syncthreads();
        if (t + 2 < NKT) {
            int s = (t + 2) % 3;
            cp16(as_addr[s], Ap + (t + 2) * 16, aok);
            cp16(bs_addr[s], Wp + (size_t)((t + 2) * 16) * LDW, true);
        }
        cp_commit();

        int s = t % 3;
        uint32_t asb = smem_u32(&As[s][0][0]);
        uint32_t bsb = smem_u32(&Bs[s][0][0]);
        uint32_t af[4][4], bf[4][2];
        #pragma unroll
        for (int mt = 0; mt < 4; ++mt)
            ldsm_x4(af[mt], asb + (uint32_t)(((m0 + mt*16 + la_row) * AS_H + la_col) * 2));
        #pragma unroll
        for (int nt = 0; nt < 4; ++nt)
            ldsm_x2_trans(bf[nt][0], bf[nt][1],
                          bsb + (uint32_t)((lrowB * BS_H + n0 + nt * 8) * 2));
        #pragma unroll
        for (int mt = 0; mt < 4; ++mt)
            #pragma unroll
            for (int nt = 0; nt < 4; ++nt)
                mma_f16(c[mt][nt], af[mt], bf[nt]);
        __syncthreads();
    }

    int colbase = bcol + n0;
    int s  = colbase / NC;
    int hd = colbase - s * NC;
    int h  = hd >> 6;

    #pragma unroll
    for (int mt = 0; mt < 4; ++mt) {
        #pragma unroll
        for (int half = 0; half < 2; ++half) {
            int m = brow + m0 + mt * 16 + gid + half * 8;
            if (m >= MROWS) continue;
            if (SCATTER) {
                int b  = m / NTOK;
                int n  = m - b * NTOK;
                int bh = b * NHEAD + h;
                __half* dst = nullptr;
                if (s == 0) {
                    dst = &g_qh[((size_t)bh * NTOK + n) * ND];
                } else {
                    int dest = g_dest[bh * NTOK + n];
                    if (dest >= 0)
                        dst = &((s == 1) ? g_kph : g_vph)[((size_t)bh * NKEEP + dest) * ND];
                }
                if (!dst) continue;
                int d_off = hd & 63;
                #pragma unroll
                for (int nt = 0; nt < 4; ++nt) {
                    int cl = nt * 8 + tid4 * 2;
                    float2 bv = *(const float2*)(bias + colbase + cl);
                    *(__half2*)(dst + d_off + cl) =
                        __floats2half2_rn(c[mt][nt][half*2+0] + bv.x,
                                          c[mt][nt][half*2+1] + bv.y);
                }
            } else {
                float* dst = out + (size_t)m * LDW + colbase;
                #pragma unroll
                for (int nt = 0; nt < 4; ++nt) {
                    int cl = nt * 8 + tid4 * 2;
                    float2 bv = *(const float2*)(bias + colbase + cl);
                    float2 o;
                    o.x = c[mt][nt][half*2+0] + bv.x;
                    o.y = c[mt][nt][half*2+1] + bv.y;
                    *(float2*)(dst + cl) = o;
                }
            }
        }
    }
}

// ---------------- attention: half-S buffer, 3-pass softmax, 2 CTAs/SM ----------
#define QK_H 72
#define PS_H 312
#define ATTN_SMEM (32*QK_H*2 + NPAD*QK_H*2 + NPAD2*QK_H*2 + 32*PS_H*2)

__global__ __launch_bounds__(256, 2) void attn_mma()
{
    extern __shared__ __align__(16) char sm[];
    __half* Qh = (__half*)sm;                          // 32 x 72
    __half* Kh = Qh + 32 * QK_H;                       // 296 x 72
    __half* Vh = Kh + NPAD * QK_H;                     // 304 x 72
    __half* Ps = Vh + NPAD2 * QK_H;                    // 32 x 312 (S then P)

    int tid  = threadIdx.x;
    int bh   = blockIdx.x;
    int wid  = tid >> 5;
    int lane = tid & 31;
    int gid  = lane >> 2;
    int t4   = lane & 3;

    int la_row = lane & 15;
    int la_col = (lane >> 4) << 3;
    int lk_row = lane & 7;
    int lk_col = ((lane >> 3) & 1) << 3;

    const __half* kp = g_kph + (size_t)bh * NKEEP * ND;
    const __half* vp = g_vph + (size_t)bh * NKEEP * ND;
    const uint4 zu4 = make_uint4(0u, 0u, 0u, 0u);
    for (int idx = tid; idx < NPAD2 * 8; idx += 256) {
        int m = idx >> 3, ch = (idx & 7) << 3;
        uint4 vv = (m < NKEEP) ? *(const uint4*)(vp + (size_t)m * ND + ch) : zu4;
        *(uint4*)&Vh[m * QK_H + ch] = vv;
        if (m < NPAD) {
            uint4 kv = (m < NKEEP) ? *(const uint4*)(kp + (size_t)m * ND + ch) : zu4;
            *(uint4*)&Kh[m * QK_H + ch] = kv;
        }
    }
    // zero Ps pad cols [NPAD, NPAD2): Phase A covers only up to NPAD
    for (int idx = tid; idx < 32 * (NPAD2 - NPAD); idx += 256) {
        int r = idx / (NPAD2 - NPAD), cl = NPAD + idx % (NPAD2 - NPAD);
        Ps[r * PS_H + cl] = __float2half(0.f);
    }
    const __half* qp = g_qh + (size_t)bh * NTOK * ND;
    int b = bh / NHEAD, h = bh - b * NHEAD;
    uint32_t qh_base = smem_u32(Qh);
    uint32_t kh_base = smem_u32(Kh);
    uint32_t vh_base = smem_u32(Vh);
    uint32_t ps_base = smem_u32(Ps);

    for (int q0 = 0; q0 < NTOK; q0 += 32) {
        {
            int m = tid >> 3, ch = (tid & 7) << 3;
            int qg = q0 + m;
            uint4 qv = (qg < NTOK) ? *(const uint4*)(qp + (size_t)qg * ND + ch) : zu4;
            *(uint4*)&Qh[m * QK_H + ch] = qv;
        }
        __syncthreads();

        // Phase A: S = (Q K^T) * scale -> half into Ps
        {
            int wm = wid & 1, wn = wid >> 1;
            int m0 = wm * 16;
            float c[10][4];
            #pragma unroll
            for (int i = 0; i < 10; ++i)
                c[i][0] = c[i][1] = c[i][2] = c[i][3] = 0.f;
            #pragma unroll
            for (int ks = 0; ks < 4; ++ks) {
                int k0 = ks * 16;
                uint32_t a[4];
                ldsm_x4(a, qh_base + (uint32_t)(((m0 + la_row) * QK_H + k0 + la_col) * 2));
                #pragma unroll
                for (int i = 0; i < 10; ++i) {
                    int nt = wn + 4 * i;
                    if (nt >= NT8) break;
                    int nb = nt * 8;
                    uint32_t bb[2];
                    ldsm_x2(bb[0], bb[1],
                            kh_base + (uint32_t)(((nb + lk_row) * QK_H + k0 + lk_col) * 2));
                    mma_f16(c[i], a, bb);
                }
            }
            #pragma unroll
            for (int i = 0; i < 10; ++i) {
                int nt = wn + 4 * i;
                if (nt >= NT8) break;
                int nb = nt * 8;
                *(__half2*)&Ps[(m0 + gid) * PS_H + nb + 2 * t4]
                    = __floats2half2_rn(c[i][0] * 0.125f, c[i][1] * 0.125f);
                *(__half2*)&Ps[(m0 + gid + 8) * PS_H + nb + 2 * t4]
                    = __floats2half2_rn(c[i][2] * 0.125f, c[i][3] * 0.125f);
            }
        }
        __syncthreads();

        // Phase B: 3-pass max-subtracted softmax on half S, f32 math, 1 exp/elem
        {
            int w = tid >> 5, ln = tid & 31;
            #pragma unroll
            for (int r = 0; r < 4; ++r) {
                __half* Pr = Ps + (w * 4 + r) * PS_H;
                float mx = -3.0e38f;
                for (int m = ln; m < NKEEP; m += 32)
                    mx = fmaxf(mx, __half2float(Pr[m]));
                #pragma unroll
                for (int o = 16; o; o >>= 1) mx = fmaxf(mx, __shfl_xor_sync(0xffffffffu, mx, o));
                float sum = 0.f;
                for (int m = ln; m < NKEEP; m += 32) {
                    float e = __expf(__half2float(Pr[m]) - mx);
                    Pr[m] = __float2half(e);
                    sum += e;
                }
                #pragma unroll
                for (int o = 16; o; o >>= 1) sum += __shfl_xor_sync(0xffffffffu, sum, o);
                float inv = 1.f / sum;
                for (int m = ln; m < NKEEP; m += 32)
                    Pr[m] = __float2half(__half2float(Pr[m]) * inv);
            }
        }
        __syncthreads();

        // Phase C: O = P @ V; P via ldsm.x4, V via ldsm.x2.trans
        {
            int wm = wid & 1, wn = wid >> 1;
            int m0 = wm * 16, n0 = wn * 16;
            float c[2][4];
            #pragma unroll
            for (int nt = 0; nt < 2; ++nt)
                #pragma unroll
                for (int r = 0; r < 4; ++r) c[nt][r] = 0.f;

            int lrow = (lane & 7) + ((lane >> 3) & 1) * 8;

            for (int ks = 0; ks < NPAD2 / 16; ++ks) {
                int k0 = ks * 16;
                uint32_t a[4];
                ldsm_x4(a, ps_base + (uint32_t)(((m0 + la_row) * PS_H + k0 + la_col) * 2));
                #pragma unroll
                for (int nt = 0; nt < 2; ++nt) {
                    uint32_t bb[2];
                    uint32_t addr = vh_base + (uint32_t)(((k0 + lrow) * QK_H + n0 + nt * 8) * 2);
                    ldsm_x2_trans(bb[0], bb[1], addr);
                    mma_f16(c[nt], a, bb);
                }
            }

            #pragma unroll
            for (int half = 0; half < 2; ++half) {
                int qg = q0 + m0 + gid + half * 8;
                if (qg >= NTOK) continue;
                __half* dst = &g_aoh[((size_t)(b * NTOK + qg)) * NC + h * ND + n0];
                #pragma unroll
                for (int nt = 0; nt < 2; ++nt) {
                    *(__half2*)(dst + nt * 8 + 2 * t4) =
                        __floats2half2_rn(c[nt][half*2+0], c[nt][half*2+1]);
                }
            }
        }
        __syncthreads();
    }
}

// ---------------- launch -------------------------------------------------------
extern "C" void kernel_launch(void* const* d_in, const int* in_sizes, int n_in,
                              void* d_out, int out_size)
{
    const float* x     = (const float*)d_in[0];
    const float* mask  = (const float*)d_in[1];
    const float* Wqkv  = (const float*)d_in[2];
    const float* bqkv  = (const float*)d_in[3];
    const float* Wproj = (const float*)d_in[4];
    const float* bproj = (const float*)d_in[5];
    float* out = (float*)d_out;

    __half *xh, *wqkvh, *wprojh, *aoh;
    cudaGetSymbolAddress((void**)&xh,     g_xh);
    cudaGetSymbolAddress((void**)&wqkvh,  g_wqkvh);
    cudaGetSymbolAddress((void**)&wprojh, g_wprojh);
    cudaGetSymbolAddress((void**)&aoh,    g_aoh);

    {
        int n1 = MROWS * NC, n2 = NC * QCOLS, n3 = NC * NC;
        f2h_kernel<<<(n1 / 4 + 255) / 256, 256>>>(x,     xh,     n1);
        f2h_kernel<<<(n2 / 4 + 255) / 256, 256>>>(Wqkv,  wqkvh,  n2);
        f2h_kernel<<<(n3 / 4 + 255) / 256, 256>>>(Wproj, wprojh, n3);
    }

    select_kernel<<<NB * NHEAD, 256>>>(mask);

    dim3 g1(QCOLS / 128, (MROWS + 127) / 128);
    gemm_cp<QCOLS, true><<<g1, 256>>>(xh, wqkvh, bqkv, nullptr);

    cudaFuncSetAttribute(attn_mma, cudaFuncAttributeMaxDynamicSharedMemorySize, ATTN_SMEM);
    attn_mma<<<NB * NHEAD, 256, ATTN_SMEM>>>();

    dim3 g2(NC / 128, (MROWS + 127) / 128);
    gemm_cp<NC, false><<<g2, 256>>>(aoh, wprojh, bproj, out);
}